// round 3
// baseline (speedup 1.0000x reference)
#include <cuda_runtime.h>
#include <cuda_bf16.h>

#define RPB   32                 // rows per block
#define JT    12                 // threads in j-dim (each handles 2 of 24 scales)
#define BLOCK (JT * RPB)         // 384

#define PI_F 3.14159265358979f

// Abramowitz-Stegun 4.4.45: acos(x) ~= sqrt(1-x)*poly3(x) on [0,1], abs err 6.7e-5.
// Extended to [-1,1] via acos(-x) = pi - acos(x).
__device__ __forceinline__ float acos_fast(float x) {
    float ax = fabsf(x);
    float p = fmaf(ax, -0.0187293f, 0.0742610f);
    p = fmaf(ax, p, -0.2121144f);
    p = fmaf(ax, p,  1.5707288f);
    float r = sqrtf(1.0f - ax) * p;
    return (x < 0.0f) ? (PI_F - r) : r;
}

__global__ __launch_bounds__(BLOCK, 4)
void giou_loss_kernel(const float* __restrict__ pred,
                      const float* __restrict__ target,
                      float* __restrict__ out, int N) {
    __shared__ __align__(16) float s_t[RPB * 50];
    __shared__ __align__(16) float s_p[RPB * 26];
    __shared__ float s_dist[RPB];

    const int r0  = blockIdx.x * RPB;
    const int tid = threadIdx.y * JT + threadIdx.x;
    const int rows = min(RPB, N - r0);
    if (rows <= 0) return;

    // ---- Stage tiles into smem (coalesced float4 loads on the full-tile path) ----
    if (rows == RPB) {
        const float4* tg = reinterpret_cast<const float4*>(target + (size_t)r0 * 50);
        float4* st4 = reinterpret_cast<float4*>(s_t);
        for (int i = tid; i < RPB * 50 / 4; i += BLOCK) st4[i] = tg[i];
        const float4* pg = reinterpret_cast<const float4*>(pred + (size_t)r0 * 26);
        float4* sp4 = reinterpret_cast<float4*>(s_p);
        for (int i = tid; i < RPB * 26 / 4; i += BLOCK) sp4[i] = pg[i];
    } else {
        for (int i = tid; i < rows * 50; i += BLOCK) s_t[i] = target[(size_t)r0 * 50 + i];
        for (int i = tid; i < rows * 26; i += BLOCK) s_p[i] = pred[(size_t)r0 * 26 + i];
    }
    __syncthreads();

    // ---- Per-row: dist, pd_cx/pd_cy outputs ----
    if (tid < rows) {
        float pcx = s_p[tid * 26 + 0];
        float pcy = s_p[tid * 26 + 1];
        float gcx = s_t[tid * 50 + 0];
        float gcy = s_t[tid * 50 + 1];
        float dx = gcx - pcx, dy = gcy - pcy;
        s_dist[tid] = sqrtf(fmaf(dx, dx, dy * dy));
        out[(size_t)N * 24 + r0 + tid] = pcx;
        out[(size_t)N * 25 + r0 + tid] = pcy;
    }
    __syncthreads();

    // ---- Compute: thread (tx, ty) handles row ty, scales j0 = 2*tx and j0+1 ----
    const int r  = threadIdx.y;
    if (r >= rows) return;
    const int j0 = 2 * threadIdx.x;

    // Per-row values (register-resident, shared by both items)
    const float2 cxy  = *reinterpret_cast<const float2*>(s_t + r * 50);       // gt_cx, gt_cy
    const float2 gxy0 = *reinterpret_cast<const float2*>(s_t + r * 50 + 2 + 2 * j0);
    const float2 gxy1 = *reinterpret_cast<const float2*>(s_t + r * 50 + 4 + 2 * j0);
    const float2 sp2  = *reinterpret_cast<const float2*>(s_p + r * 26 + 2 + j0);
    const float dist  = s_dist[r];
    const float d2    = dist * dist;
    const float twod  = 2.0f * dist;

    float loss[2], spv[2];
    #pragma unroll
    for (int k = 0; k < 2; k++) {
        const float gx = k ? gxy1.x : gxy0.x;
        const float gy = k ? gxy1.y : gxy0.y;
        const float sp = k ? sp2.y  : sp2.x;

        const float vx = gx - cxy.x, vy = gy - cxy.y;
        const float sg = sqrtf(fmaf(vx, vx, vy * vy));     // scale_gt

        const float minr  = fminf(sg, sp);
        const float maxr  = fmaxf(sg, sp);
        const float minr2 = minr * minr;
        const float maxr2 = maxr * maxr;
        const float diff  = maxr2 - minr2;

        float acmin = __fdividef(d2 - diff, fmaf(minr, twod, 1e-8f));
        float acmax = __fdividef(d2 + diff, fmaf(maxr, twod, 1e-8f));
        acmin = fminf(fmaxf(acmin, -0.99f), 0.99f);
        acmax = fminf(fmaxf(acmax, -0.99f), 0.99f);

        const float ang_min = acos_fast(acmin);
        const float ang_max = acos_fast(acmax);
        // sin(acos(x)) = sqrt(1 - x^2), exact for angle in [0, pi]
        const float sin_min = sqrtf(fmaxf(fmaf(-acmin, acmin, 1.0f), 0.0f));

        const float inter = fmaf(ang_min, minr2,
                           fmaf(ang_max, maxr2, -(minr * dist) * sin_min));

        const float sum       = sg + sp;
        const bool  contained = fabsf(sg - sp) >= dist;
        const bool  disjoint  = dist >= sum;
        const float res  = disjoint ? 0.0f : (contained ? PI_F * minr2 : inter);

        const float area = PI_F * (minr2 + maxr2);          // area_gt + area_pd
        const float u    = area - res;
        const float iou  = __fdividef(res, u + 1e-6f);

        const float cl = contained ? maxr : 0.5f * (sum + dist);
        const float cs = PI_F * cl * cl;
        // giou = iou - (cs - u)/cs = iou - 1 + u/cs ; loss = 1 - giou = 2 - iou - u/cs
        loss[k] = 2.0f - iou - __fdividef(u, cs);
        spv[k]  = sp;
    }

    const size_t base = (size_t)(r0 + r) * 24 + j0;
    *reinterpret_cast<float2*>(out + base)                   = make_float2(loss[0], loss[1]);
    *reinterpret_cast<float2*>(out + (size_t)N * 26 + base)  = make_float2(spv[0],  spv[1]);
}

extern "C" void kernel_launch(void* const* d_in, const int* in_sizes, int n_in,
                              void* d_out, int out_size) {
    const float* pred   = (const float*)d_in[0];
    const float* target = (const float*)d_in[1];
    float* out = (float*)d_out;
    int N = in_sizes[0] / 26;
    int grid = (N + RPB - 1) / RPB;
    giou_loss_kernel<<<grid, dim3(JT, RPB)>>>(pred, target, out, N);
}

// round 4
// speedup vs baseline: 1.3981x; 1.3981x over previous
#include <cuda_runtime.h>
#include <cuda_bf16.h>

#define RPB   32                 // rows per block
#define BLOCK 256                // 8 threads per row, 3 items each

#define PI_F 3.14159265358979f

// Abramowitz-Stegun 4.4.45: acos(x) ~= sqrt(1-x)*poly3(x) on [0,1], abs err 6.7e-5.
// Extended to [-1,1] via acos(-x) = pi - acos(x).
__device__ __forceinline__ float acos_fast(float x) {
    float ax = fabsf(x);
    float p = fmaf(ax, -0.0187293f, 0.0742610f);
    p = fmaf(ax, p, -0.2121144f);
    p = fmaf(ax, p,  1.5707288f);
    float r = sqrtf(1.0f - ax) * p;
    return (x < 0.0f) ? (PI_F - r) : r;
}

__global__ __launch_bounds__(BLOCK, 8)
void giou_loss_kernel(const float* __restrict__ pred,
                      const float* __restrict__ target,
                      float* __restrict__ out, int N) {
    __shared__ __align__(16) float s_t[RPB * 50];
    __shared__ __align__(16) float s_p[RPB * 26];

    const int r0  = blockIdx.x * RPB;
    const int tid = threadIdx.x;
    const int rows = min(RPB, N - r0);
    if (rows <= 0) return;

    // ---- Stage tiles into smem (coalesced float4 loads on the full-tile path) ----
    if (rows == RPB) {
        const float4* tg = reinterpret_cast<const float4*>(target + (size_t)r0 * 50);
        float4* st4 = reinterpret_cast<float4*>(s_t);
        for (int i = tid; i < RPB * 50 / 4; i += BLOCK) st4[i] = tg[i];
        const float4* pg = reinterpret_cast<const float4*>(pred + (size_t)r0 * 26);
        float4* sp4 = reinterpret_cast<float4*>(s_p);
        for (int i = tid; i < RPB * 26 / 4; i += BLOCK) sp4[i] = pg[i];
    } else {
        for (int i = tid; i < rows * 50; i += BLOCK) s_t[i] = target[(size_t)r0 * 50 + i];
        for (int i = tid; i < rows * 26; i += BLOCK) s_p[i] = pred[(size_t)r0 * 26 + i];
    }
    __syncthreads();

    // ---- pd_cx / pd_cy outputs (coalesced, one thread per row) ----
    if (tid < rows) {
        out[(size_t)N * 24 + r0 + tid] = s_p[tid * 26 + 0];
        out[(size_t)N * 25 + r0 + tid] = s_p[tid * 26 + 1];
    }

    // ---- Compute: thread handles row (tid>>3), scales j = (tid&7) + 8k, k=0..2 ----
    const int r  = tid >> 3;
    if (r >= rows) return;
    const int jb = tid & 7;

    const float* t = s_t + r * 50;
    const float* p = s_p + r * 26;

    // Per-row values (register-resident, shared by all 3 items)
    const float gt_cx = t[0], gt_cy = t[1];
    const float pd_cx = p[0], pd_cy = p[1];
    const float ddx = gt_cx - pd_cx, ddy = gt_cy - pd_cy;
    const float dist = sqrtf(fmaf(ddx, ddx, ddy * ddy));
    const float d2   = dist * dist;
    const float twod = 2.0f * dist;

    float* __restrict__ out_loss  = out + (size_t)(r0 + r) * 24;
    float* __restrict__ out_scale = out + (size_t)N * 26 + (size_t)(r0 + r) * 24;

    #pragma unroll
    for (int k = 0; k < 3; k++) {
        const int j = jb + 8 * k;
        const float gx = t[2 + 2 * j];
        const float gy = t[3 + 2 * j];
        const float sp = p[2 + j];

        const float vx = gx - gt_cx, vy = gy - gt_cy;
        const float sg = sqrtf(fmaf(vx, vx, vy * vy));     // scale_gt

        const float minr  = fminf(sg, sp);
        const float maxr  = fmaxf(sg, sp);
        const float minr2 = minr * minr;
        const float maxr2 = maxr * maxr;
        const float diff  = maxr2 - minr2;

        float acmin = __fdividef(d2 - diff, fmaf(minr, twod, 1e-8f));
        float acmax = __fdividef(d2 + diff, fmaf(maxr, twod, 1e-8f));
        acmin = fminf(fmaxf(acmin, -0.99f), 0.99f);
        acmax = fminf(fmaxf(acmax, -0.99f), 0.99f);

        const float ang_min = acos_fast(acmin);
        const float ang_max = acos_fast(acmax);
        // sin(acos(x)) = sqrt(1 - x^2), exact for angle in [0, pi]
        const float sin_min = sqrtf(fmaxf(fmaf(-acmin, acmin, 1.0f), 0.0f));

        const float inter = fmaf(ang_min, minr2,
                           fmaf(ang_max, maxr2, -(minr * dist) * sin_min));

        const float sum       = sg + sp;
        const bool  contained = fabsf(sg - sp) >= dist;
        const bool  disjoint  = dist >= sum;
        const float res  = disjoint ? 0.0f : (contained ? PI_F * minr2 : inter);

        const float area = PI_F * (minr2 + maxr2);          // area_gt + area_pd
        const float u    = area - res;
        const float iou  = __fdividef(res, u + 1e-6f);

        const float cl = contained ? maxr : 0.5f * (sum + dist);
        const float cs = PI_F * cl * cl;
        // giou = iou - (cs - u)/cs = iou - 1 + u/cs ; loss = 1 - giou = 2 - iou - u/cs
        out_loss [j] = 2.0f - iou - __fdividef(u, cs);
        out_scale[j] = sp;
    }
}

extern "C" void kernel_launch(void* const* d_in, const int* in_sizes, int n_in,
                              void* d_out, int out_size) {
    const float* pred   = (const float*)d_in[0];
    const float* target = (const float*)d_in[1];
    float* out = (float*)d_out;
    int N = in_sizes[0] / 26;
    int grid = (N + RPB - 1) / RPB;
    giou_loss_kernel<<<grid, BLOCK>>>(pred, target, out, N);
}

// round 5
// speedup vs baseline: 1.4684x; 1.0503x over previous
#include <cuda_runtime.h>
#include <cuda_bf16.h>

#define RPB   32                 // rows per block
#define BLOCK 256                // 8 threads per row, 3 items each

#define PI_F 3.14159265358979f

// Single-instruction MUFU sqrt (args are always >= 0 here). Max rel err ~1e-7.
__device__ __forceinline__ float fsqrt_fast(float x) {
    float y;
    asm("sqrt.approx.f32 %0, %1;" : "=f"(y) : "f"(x));
    return y;
}

// Abramowitz-Stegun 4.4.45: acos(x) ~= sqrt(1-x)*poly3(x) on [0,1], abs err 6.7e-5.
// Extended to [-1,1] via acos(-x) = pi - acos(x).
__device__ __forceinline__ float acos_fast(float x) {
    float ax = fabsf(x);
    float p = fmaf(ax, -0.0187293f, 0.0742610f);
    p = fmaf(ax, p, -0.2121144f);
    p = fmaf(ax, p,  1.5707288f);
    float r = fsqrt_fast(1.0f - ax) * p;
    return (x < 0.0f) ? (PI_F - r) : r;
}

__global__ __launch_bounds__(BLOCK, 8)
void giou_loss_kernel(const float* __restrict__ pred,
                      const float* __restrict__ target,
                      float* __restrict__ out, int N) {
    __shared__ __align__(16) float s_t[RPB * 50];
    __shared__ __align__(16) float s_p[RPB * 26];

    const int r0  = blockIdx.x * RPB;
    const int tid = threadIdx.x;
    const int rows = min(RPB, N - r0);
    if (rows <= 0) return;

    // ---- Stage tiles into smem (coalesced float4 loads on the full-tile path) ----
    if (rows == RPB) {
        const float4* tg = reinterpret_cast<const float4*>(target + (size_t)r0 * 50);
        float4* st4 = reinterpret_cast<float4*>(s_t);
        for (int i = tid; i < RPB * 50 / 4; i += BLOCK) st4[i] = tg[i];
        const float4* pg = reinterpret_cast<const float4*>(pred + (size_t)r0 * 26);
        float4* sp4 = reinterpret_cast<float4*>(s_p);
        for (int i = tid; i < RPB * 26 / 4; i += BLOCK) sp4[i] = pg[i];
    } else {
        for (int i = tid; i < rows * 50; i += BLOCK) s_t[i] = target[(size_t)r0 * 50 + i];
        for (int i = tid; i < rows * 26; i += BLOCK) s_p[i] = pred[(size_t)r0 * 26 + i];
    }
    __syncthreads();

    // ---- pd_cx / pd_cy outputs (coalesced, one thread per row) ----
    if (tid < rows) {
        out[(size_t)N * 24 + r0 + tid] = s_p[tid * 26 + 0];
        out[(size_t)N * 25 + r0 + tid] = s_p[tid * 26 + 1];
    }

    // ---- Compute: thread handles row (tid>>3), scales j = (tid&7) + 8k, k=0..2 ----
    const int r  = tid >> 3;
    if (r >= rows) return;
    const int jb = tid & 7;

    const float* t = s_t + r * 50;
    const float* p = s_p + r * 26;

    // Per-row values (register-resident, shared by all 3 items)
    const float2 gc  = *reinterpret_cast<const float2*>(t);      // gt_cx, gt_cy
    const float2 pc  = *reinterpret_cast<const float2*>(p);      // pd_cx, pd_cy
    const float ddx = gc.x - pc.x, ddy = gc.y - pc.y;
    const float dist = fsqrt_fast(fmaf(ddx, ddx, ddy * ddy));
    const float d2   = dist * dist;
    const float twod = 2.0f * dist;

    // Base pointers for this thread's strided item set
    const float2* gxy_base = reinterpret_cast<const float2*>(t + 2 + 2 * jb); // stride 8 float2
    const float*  sp_base  = p + 2 + jb;                                      // stride 8 floats

    float* __restrict__ out_loss  = out + (size_t)(r0 + r) * 24 + jb;
    float* __restrict__ out_scale = out + (size_t)N * 26 + (size_t)(r0 + r) * 24 + jb;

    #pragma unroll
    for (int k = 0; k < 3; k++) {
        const float2 gxy = gxy_base[8 * k];
        const float  sp  = sp_base [8 * k];

        const float vx = gxy.x - gc.x, vy = gxy.y - gc.y;
        const float sg = fsqrt_fast(fmaf(vx, vx, vy * vy));   // scale_gt

        const float minr  = fminf(sg, sp);
        const float maxr  = fmaxf(sg, sp);
        const float minr2 = minr * minr;
        const float maxr2 = maxr * maxr;
        const float diff  = maxr2 - minr2;

        float acmin = __fdividef(d2 - diff, fmaf(minr, twod, 1e-8f));
        float acmax = __fdividef(d2 + diff, fmaf(maxr, twod, 1e-8f));
        acmin = fminf(fmaxf(acmin, -0.99f), 0.99f);
        acmax = fminf(fmaxf(acmax, -0.99f), 0.99f);

        const float ang_min = acos_fast(acmin);
        const float ang_max = acos_fast(acmax);
        // sin(acos(x)) = sqrt(1 - x^2), exact for angle in [0, pi]
        const float sin_min = fsqrt_fast(fmaxf(fmaf(-acmin, acmin, 1.0f), 0.0f));

        const float inter = fmaf(ang_min, minr2,
                           fmaf(ang_max, maxr2, -(minr * dist) * sin_min));

        const float sum       = sg + sp;
        const bool  contained = fabsf(sg - sp) >= dist;
        const bool  disjoint  = dist >= sum;
        const float res  = disjoint ? 0.0f : (contained ? PI_F * minr2 : inter);

        const float area = PI_F * (minr2 + maxr2);            // area_gt + area_pd
        const float u    = area - res;
        const float iou  = __fdividef(res, u + 1e-6f);

        const float cl = contained ? maxr : 0.5f * (sum + dist);
        const float cs = PI_F * cl * cl;
        // giou = iou - (cs - u)/cs = iou - 1 + u/cs ; loss = 1 - giou = 2 - iou - u/cs
        out_loss [8 * k] = 2.0f - iou - __fdividef(u, cs);
        out_scale[8 * k] = sp;
    }
}

extern "C" void kernel_launch(void* const* d_in, const int* in_sizes, int n_in,
                              void* d_out, int out_size) {
    const float* pred   = (const float*)d_in[0];
    const float* target = (const float*)d_in[1];
    float* out = (float*)d_out;
    int N = in_sizes[0] / 26;
    int grid = (N + RPB - 1) / RPB;
    giou_loss_kernel<<<grid, BLOCK>>>(pred, target, out, N);
}

// round 6
// speedup vs baseline: 1.8077x; 1.2311x over previous
#include <cuda_runtime.h>
#include <cuda_bf16.h>

#define BLOCK 256                // 8 threads per row, 3 items each

#define PI_F 3.14159265358979f

// Single-instruction MUFU sqrt (args are always >= 0 here). Max rel err ~1e-7.
__device__ __forceinline__ float fsqrt_fast(float x) {
    float y;
    asm("sqrt.approx.f32 %0, %1;" : "=f"(y) : "f"(x));
    return y;
}
__device__ __forceinline__ float frcp_fast(float x) {
    float y;
    asm("rcp.approx.f32 %0, %1;" : "=f"(y) : "f"(x));
    return y;
}

// Abramowitz-Stegun 4.4.45: acos(x) ~= sqrt(1-x)*poly3(x) on [0,1], abs err 6.7e-5.
// Extended to [-1,1] via acos(-x) = pi - acos(x).
__device__ __forceinline__ float acos_fast(float x) {
    float ax = fabsf(x);
    float p = fmaf(ax, -0.0187293f, 0.0742610f);
    p = fmaf(ax, p, -0.2121144f);
    p = fmaf(ax, p,  1.5707288f);
    float r = fsqrt_fast(1.0f - ax) * p;
    return (x < 0.0f) ? (PI_F - r) : r;
}

__global__ __launch_bounds__(BLOCK, 8)
void giou_loss_kernel(const float* __restrict__ pred,
                      const float* __restrict__ target,
                      float* __restrict__ out, int N) {
    const int gid = blockIdx.x * BLOCK + threadIdx.x;
    const int row = gid >> 3;          // one row per 8 threads
    const int jb  = gid & 7;           // this thread: j = jb, jb+8, jb+16
    if (row >= N) return;

    const float* __restrict__ t = target + (size_t)row * 50;
    const float* __restrict__ p = pred   + (size_t)row * 26;

    // Row headers (L1-broadcast across the 8 lanes of this row)
    const float2 gc = *reinterpret_cast<const float2*>(t);   // gt_cx, gt_cy
    const float2 pc = *reinterpret_cast<const float2*>(p);   // pd_cx, pd_cy

    const float ddx = gc.x - pc.x, ddy = gc.y - pc.y;
    const float dist = fsqrt_fast(fmaf(ddx, ddx, ddy * ddy));
    const float d2   = dist * dist;
    const float twod = 2.0f * dist;

    // pd_cx / pd_cy outputs (one lane per row; 1 sector per warp per stream)
    if (jb == 0) {
        out[(size_t)N * 24 + row] = pc.x;
        out[(size_t)N * 25 + row] = pc.y;
    }

    const float2* __restrict__ gxy_base = reinterpret_cast<const float2*>(t + 2 + 2 * jb);
    const float*  __restrict__ sp_base  = p + 2 + jb;
    float* __restrict__ out_loss  = out + (size_t)row * 24 + jb;
    float* __restrict__ out_scale = out + (size_t)N * 26 + (size_t)row * 24 + jb;

    #pragma unroll
    for (int k = 0; k < 3; k++) {
        const float2 gxy = gxy_base[8 * k];
        const float  sp  = sp_base [8 * k];

        const float vx = gxy.x - gc.x, vy = gxy.y - gc.y;
        const float sg = fsqrt_fast(fmaf(vx, vx, vy * vy));   // scale_gt

        const float minr  = fminf(sg, sp);
        const float maxr  = fmaxf(sg, sp);
        const float minr2 = minr * minr;
        const float maxr2 = maxr * maxr;
        const float diff  = maxr2 - minr2;

        // Shared reciprocal: 1/(2d*minr*maxr); acmin = (d2-diff)*maxr*t, etc.
        const float rinv = frcp_fast(twod * minr * maxr);
        float acmin = (d2 - diff) * maxr * rinv;
        float acmax = (d2 + diff) * minr * rinv;
        acmin = fminf(fmaxf(acmin, -0.99f), 0.99f);
        acmax = fminf(fmaxf(acmax, -0.99f), 0.99f);

        const float ang_min = acos_fast(acmin);
        const float ang_max = acos_fast(acmax);
        // sin(acos(x)) = sqrt(1 - x^2), exact for angle in [0, pi]
        const float sin_min = fsqrt_fast(fmaxf(fmaf(-acmin, acmin, 1.0f), 0.0f));

        const float inter = fmaf(ang_min, minr2,
                           fmaf(ang_max, maxr2, -(minr * dist) * sin_min));

        const float sum       = sg + sp;
        const bool  contained = fabsf(sg - sp) >= dist;
        const bool  disjoint  = dist >= sum;
        const float res  = disjoint ? 0.0f : (contained ? PI_F * minr2 : inter);

        const float area = PI_F * (minr2 + maxr2);            // area_gt + area_pd
        const float u    = area - res;
        const float iou  = (res) * frcp_fast(u + 1e-6f);

        const float cl = contained ? maxr : 0.5f * (sum + dist);
        const float cs = PI_F * cl * cl;
        // giou = iou - (cs - u)/cs = iou - 1 + u/cs ; loss = 1 - giou = 2 - iou - u/cs
        out_loss [8 * k] = 2.0f - iou - u * frcp_fast(cs);
        out_scale[8 * k] = sp;
    }
}

extern "C" void kernel_launch(void* const* d_in, const int* in_sizes, int n_in,
                              void* d_out, int out_size) {
    const float* pred   = (const float*)d_in[0];
    const float* target = (const float*)d_in[1];
    float* out = (float*)d_out;
    int N = in_sizes[0] / 26;
    long long threads = (long long)N * 8;
    int grid = (int)((threads + BLOCK - 1) / BLOCK);
    giou_loss_kernel<<<grid, BLOCK>>>(pred, target, out, N);
}